// round 10
// baseline (speedup 1.0000x reference)
#include <cuda_runtime.h>
#include <cstdint>

// Problem constants (from reference):
//   B=256, P=4096, H=W=512
// Inputs (metadata order):
//   d_in[0]: indices   int32  [B, P, 2]   (JAX x64 disabled: jnp.int64 request -> int32)
//   d_in[1]: num_valid int32  [B]
//   d_in[2]: feats     float32[B, P, 1]
// Output: float32 [B, H, W]

#define B_  256
#define P_  4096
#define H_  512
#define W_  512
#define HW_ (H_ * W_)

#define SCAT_THREADS_ 256
#define N_CHUNKS_     4

__global__ __launch_bounds__(SCAT_THREADS_)
void scatter_chunk_kernel(const int* __restrict__ indices,
                          const int* __restrict__ num_valid,
                          const float* __restrict__ feats,
                          float* __restrict__ out,
                          int b0)                    // first batch of this chunk
{
    const int i  = blockIdx.x * SCAT_THREADS_ + threadIdx.x; // point id in chunk
    const int bl = i >> 12;                                  // local batch (P_=4096)
    const int p  = i & (P_ - 1);
    const int b  = b0 + bl;

    const int nv = __ldg(num_valid + b);
    if (p < nv) {
        const size_t gi = (size_t)b * P_ + p;
        const int2 rc = reinterpret_cast<const int2*>(indices)[gi];
        const int r = rc.x;
        const int c = rc.y;
        if ((unsigned)r < H_ && (unsigned)c < W_) {
            const float v = __ldg(feats + gi);
            atomicAdd(out + (size_t)b * HW_ + r * W_ + c, v);
        }
    }
}

extern "C" void kernel_launch(void* const* d_in, const int* in_sizes, int n_in,
                              void* d_out, int out_size)
{
    const int*   indices = (const int*)d_in[0];
    const int*   nvalid  = (const int*)d_in[1];
    const float* feats   = (const float*)d_in[2];
    float*       out     = (float*)d_out;

    // Host-side objects only (no device memory). Created once, on the first
    // (uncaptured) correctness call; reused by the capture call.
    static cudaStream_t side = nullptr;
    static cudaEvent_t  ev_m[N_CHUNKS_];
    static cudaEvent_t  ev_join;
    if (side == nullptr) {
        cudaStreamCreateWithFlags(&side, cudaStreamNonBlocking);
        for (int c = 0; c < N_CHUNKS_; c++)
            cudaEventCreateWithFlags(&ev_m[c], cudaEventDisableTiming);
        cudaEventCreateWithFlags(&ev_join, cudaEventDisableTiming);
    }

    // Chunk layout over batches: later chunks smaller so the exposed tail
    // (last scatter after last memset) is minimal.
    const int off[N_CHUNKS_] = {0, 80, 160, 224};
    const int cnt[N_CHUNKS_] = {80, 80, 64, 32};

    // Main (capture) stream: memset train; record an event after each chunk.
    for (int c = 0; c < N_CHUNKS_; c++) {
        cudaMemsetAsync(out + (size_t)off[c] * HW_, 0,
                        (size_t)cnt[c] * HW_ * sizeof(float), 0);
        cudaEventRecord(ev_m[c], 0);
    }

    // Side stream: each chunk's scatter starts as soon as its memset is done,
    // overlapping the remaining memset chunks.
    for (int c = 0; c < N_CHUNKS_; c++) {
        cudaStreamWaitEvent(side, ev_m[c], 0);
        scatter_chunk_kernel<<<cnt[c] * (P_ / SCAT_THREADS_), SCAT_THREADS_, 0, side>>>(
            indices, nvalid, feats, out, off[c]);
    }

    // Join the fork back into the main stream before returning.
    cudaEventRecord(ev_join, side);
    cudaStreamWaitEvent(0, ev_join, 0);
}

// round 11
// speedup vs baseline: 1.1092x; 1.1092x over previous
#include <cuda_runtime.h>
#include <cstdint>

// Problem constants (from reference):
//   B=256, P=4096, H=W=512
// Inputs (metadata order):
//   d_in[0]: indices   int32  [B, P, 2]   (JAX x64 disabled: jnp.int64 request -> int32)
//   d_in[1]: num_valid int32  [B]
//   d_in[2]: feats     float32[B, P, 1]
// Output: float32 [B, H, W]

#define B_  256
#define P_  4096
#define H_  512
#define W_  512
#define HW_ (H_ * W_)

#define THREADS_   256
#define PPT_       8                     // points per thread
#define PTS_BLK_   (THREADS_ * PPT_)     // 2048 points per block (half a batch)
#define GRID_      (B_ * P_ / PTS_BLK_)  // 512 blocks

__global__ __launch_bounds__(THREADS_)
void scatter_ilp_kernel(const int* __restrict__ indices,
                        const int* __restrict__ num_valid,
                        const float* __restrict__ feats,
                        float* __restrict__ out)
{
    const int b    = blockIdx.x >> 1;                  // batch
    const int half = blockIdx.x & 1;                   // which half of the batch
    const int p0   = half * PTS_BLK_;                  // first point of this block

    const int nv = __ldg(num_valid + b);               // one broadcast load per block

    const int2*  ib = reinterpret_cast<const int2*>(indices) + (size_t)b * P_ + p0;
    const float* fb = feats + (size_t)b * P_ + p0;
    float* slice = out + (size_t)b * HW_;

    // Issue ALL loads upfront, unconditionally (P_=4096 fully allocated, so
    // reads past nv are safe; their results are discarded). MLP ~16.
    int2  rc[PPT_];
    float fv[PPT_];
    #pragma unroll
    for (int k = 0; k < PPT_; k++) {
        const int p = threadIdx.x + k * THREADS_;
        rc[k] = __ldg(ib + p);
        fv[k] = __ldg(fb + p);
    }

    // Predicated scatter-add (compiler emits RED, no return value).
    #pragma unroll
    for (int k = 0; k < PPT_; k++) {
        const int p = p0 + threadIdx.x + k * THREADS_;
        if (p < nv) {
            const int r = rc[k].x;
            const int c = rc[k].y;
            if ((unsigned)r < H_ && (unsigned)c < W_) {
                atomicAdd(slice + r * W_ + c, fv[k]);
            }
        }
    }
}

extern "C" void kernel_launch(void* const* d_in, const int* in_sizes, int n_in,
                              void* d_out, int out_size)
{
    const int*   indices = (const int*)d_in[0];
    const int*   nvalid  = (const int*)d_in[1];
    const float* feats   = (const float*)d_in[2];
    float*       out     = (float*)d_out;

    // Driver-optimal zero fill (measured ~5.8 TB/s on this chip).
    cudaMemsetAsync(d_out, 0, (size_t)out_size * sizeof(float));

    // High-ILP scatter: 8 points/thread, all loads issued before any atomic.
    scatter_ilp_kernel<<<GRID_, THREADS_>>>(indices, nvalid, feats, out);
}